// round 3
// baseline (speedup 1.0000x reference)
#include <cuda_runtime.h>

// Problem constants (fixed by the reference):
// N=2, C=2, H=W=D=64, R=3, WEIGHT=1, SIGMA_XY=6, SIGMA_IMG=0.1
static constexpr int H = 64, W = 64, D = 64, NN = 2;
static constexpr int NBLK = 2 * 64 * 4;   // n * i * jc  = 512 blocks

__device__ float g_partials[NBLK];
__device__ unsigned int g_count = 0;

__device__ __forceinline__ float ex2f(float x) {
    float y;
    asm("ex2.approx.ftz.f32 %0, %1;" : "=f"(y) : "f"(x));
    return y;
}

// KS = sqrt(50 * log2(e));  KS^2 * ds^2 = 50*log2e*ds^2
#define KS 8.4932180864f
#define HALFL2E 0.0200373478f  /* 0.5/36 * log2(e) */

__global__ __launch_bounds__(256) void crf_main(
    const float* __restrict__ yg, const float* __restrict__ sg,
    float* __restrict__ out)
{
    const int d4 = threadIdx.x;          // 0..15  (4 d-values each)
    const int ty = threadIdx.y;          // 0..15
    const int b  = blockIdx.x;
    const int jc = b & 3;
    const int i  = (b >> 2) & 63;
    const int n  = b >> 8;
    const int j  = jc * 16 + ty;

    const float4* __restrict__ s4 = (const float4*)sg;
    const float4* __restrict__ y4 = (const float4*)yg;

    // sample layout: ((n*H + i)*W + j)*D + d   -> float4 idx
    const int bs = (n * H + i) * (W * 16) + j * 16 + d4;
    // y channel 0: (((n*2 + 0)*H + i)*W + j)*D + d
    const int by = (n * 2 * H + i) * (W * 16) + j * 16 + d4;

    const float4 sc = s4[bs];
    const float4 yc = y4[by];

    // negated scaled sample values: na = -KS * s_center
    const float na0 = -KS * sc.x, na1 = -KS * sc.y;
    const float na2 = -KS * sc.z, na3 = -KS * sc.w;
    const float yp0 = yc.x, yp1 = yc.y, yp2 = yc.z, yp3 = yc.w;
    const float m0 = -2.0f * yp0, m1 = -2.0f * yp1;
    const float m2 = -2.0f * yp2, m3 = -2.0f * yp3;

    float acc = 0.0f;

    // Unordered in-bounds pairs: positive offsets only, doubled at the end.
    #pragma unroll
    for (int di = 0; di <= 3; ++di) {
        #pragma unroll
        for (int dj = -3; dj <= 3; ++dj) {
            if (di == 0 && dj <= 0) continue;   // only (0,1..3) and (1..3, -3..3)
            const float lw = -(float)(di * di + dj * dj) * HALFL2E;
            const int i2 = i + di;
            const int j2 = j + dj;
            if (i2 < H && (unsigned)j2 < (unsigned)W) {
                const int off = (di * W + dj) * 16;
                const float4 sq = s4[bs + off];
                const float4 yq = y4[by + off];

                {   float t = fmaf(KS, sq.x, na0);
                    float k = ex2f(fmaf(t, -t, lw));
                    float u = fmaf(m0, yq.x, yp0 + yq.x);
                    acc = fmaf(k, u, acc); }
                {   float t = fmaf(KS, sq.y, na1);
                    float k = ex2f(fmaf(t, -t, lw));
                    float u = fmaf(m1, yq.y, yp1 + yq.y);
                    acc = fmaf(k, u, acc); }
                {   float t = fmaf(KS, sq.z, na2);
                    float k = ex2f(fmaf(t, -t, lw));
                    float u = fmaf(m2, yq.z, yp2 + yq.z);
                    acc = fmaf(k, u, acc); }
                {   float t = fmaf(KS, sq.w, na3);
                    float k = ex2f(fmaf(t, -t, lw));
                    float u = fmaf(m3, yq.w, yp3 + yq.w);
                    acc = fmaf(k, u, acc); }
            }
        }
    }
    acc *= 2.0f;   // unordered -> directed

    // Out-of-bounds slots: neighbor features are zero-padded, so
    // k_oob = exp(-0.5*(fr^2+fc^2+fs^2)), identical for every OOB slot of a pixel.
    {
        const int ir = min(i + 3, H - 1) - max(i - 3, 0) + 1;
        const int ic = min(j + 3, W - 1) - max(j - 3, 0) + 1;
        const float cnt = (float)(49 - ir * ic);
        if (cnt > 0.0f) {
            const float cij = -(float)(i * i + j * j) * HALFL2E;
            float e = ex2f(fmaf(na0, -na0, cij))
                    + ex2f(fmaf(na1, -na1, cij))
                    + ex2f(fmaf(na2, -na2, cij))
                    + ex2f(fmaf(na3, -na3, cij));
            acc = fmaf(cnt, e, acc);
        }
    }

    // ---- Block tree reduction (deterministic) ----
    __shared__ float red[256];
    __shared__ bool is_last;
    const int tid = ty * 16 + d4;
    red[tid] = acc;
    __syncthreads();
    #pragma unroll
    for (int offr = 128; offr > 0; offr >>= 1) {
        if (tid < offr) red[tid] += red[tid + offr];
        __syncthreads();
    }

    // ---- Last-block-done global reduction (bit-deterministic: fixed order) ----
    if (tid == 0) {
        g_partials[b] = red[0];
        __threadfence();
        unsigned int v = atomicAdd(&g_count, 1u);
        is_last = (v == (unsigned)(NBLK - 1));
    }
    __syncthreads();

    if (is_last) {
        __threadfence();   // acquire: make all partials visible
        __shared__ double dred[256];
        dred[tid] = (double)g_partials[tid] + (double)g_partials[tid + 256];
        __syncthreads();
        #pragma unroll
        for (int offr = 128; offr > 0; offr >>= 1) {
            if (tid < offr) dred[tid] += dred[tid + offr];
            __syncthreads();
        }
        if (tid == 0) {
            out[0] = (float)(dred[0] / (double)(NN * D * H * W));
            g_count = 0;   // reset for next graph replay
        }
    }
}

extern "C" void kernel_launch(void* const* d_in, const int* in_sizes, int n_in,
                              void* d_out, int out_size)
{
    const float* y = (const float*)d_in[0];   // (2,2,64,64,64) softmax
    const float* s = (const float*)d_in[1];   // (2,1,64,64,64) sample
    // Defensive: identify by element count (y has 2 channels -> 2097152 elems)
    if (n_in >= 2 && in_sizes[0] == 2 * 1 * H * W * D) {
        const float* tmp = y; y = s; s = tmp;
    }

    dim3 blk(16, 16);
    crf_main<<<NBLK, blk>>>(y, s, (float*)d_out);
}

// round 4
// speedup vs baseline: 1.1569x; 1.1569x over previous
#include <cuda_runtime.h>

typedef unsigned long long u64;

// Problem constants: N=2, C=2, H=W=D=64, R=3, WEIGHT=1, SIGMA_XY=6, SIGMA_IMG=0.1
static constexpr int H = 64, W = 64, D = 64, NN = 2;
static constexpr int NBLK = 2 * 64 * 8;   // n * i * jc = 1024 blocks of 128 threads

__device__ float g_partials[NBLK];
__device__ unsigned int g_count = 0;

__device__ __forceinline__ float ex2f(float x) {
    float y;
    asm("ex2.approx.ftz.f32 %0, %1;" : "=f"(y) : "f"(x));
    return y;
}
__device__ __forceinline__ u64 pk(float a, float b) {
    u64 r; asm("mov.b64 %0, {%1, %2};" : "=l"(r) : "f"(a), "f"(b)); return r;
}
__device__ __forceinline__ void upk(float& a, float& b, u64 v) {
    asm("mov.b64 {%0, %1}, %2;" : "=f"(a), "=f"(b) : "l"(v));
}
__device__ __forceinline__ u64 fma2(u64 a, u64 b, u64 c) {
    u64 r; asm("fma.rn.f32x2 %0, %1, %2, %3;" : "=l"(r) : "l"(a), "l"(b), "l"(c)); return r;
}
__device__ __forceinline__ u64 add2(u64 a, u64 b) {
    u64 r; asm("add.rn.f32x2 %0, %1, %2;" : "=l"(r) : "l"(a), "l"(b)); return r;
}
__device__ __forceinline__ u64 mul2(u64 a, u64 b) {
    u64 r; asm("mul.rn.f32x2 %0, %1, %2;" : "=l"(r) : "l"(a), "l"(b)); return r;
}

// KS = sqrt(50 * log2(e))
#define KS 8.4932180864f
#define HALFL2E 0.0200373478f  /* 0.5/36 * log2(e) */
#define NEGBIG -1.0e30f

__global__ __launch_bounds__(128) void crf_main(
    const float* __restrict__ yg, const float* __restrict__ sg,
    float* __restrict__ out)
{
    const int d4 = threadIdx.x;          // 0..15  (4 d-values each)
    const int ty = threadIdx.y;          // 0..7
    const int b  = blockIdx.x;
    const int jc = b & 7;
    const int i  = (b >> 3) & 63;
    const int n  = b >> 9;
    const int j  = jc * 8 + ty;

    const float4* __restrict__ s4 = (const float4*)sg;
    const float4* __restrict__ y4 = (const float4*)yg;

    // sample layout: ((n*H + i)*W + j)*D + d   -> float4 index
    const int bs = (n * H + i) * (W * 16) + j * 16 + d4;
    // y channel 0: (((n*2)*H + i)*W + j)*D + d
    const int by = (n * 2 * H + i) * (W * 16) + j * 16 + d4;

    const float4 sc = s4[bs];
    const float4 yc = y4[by];

    const u64 KS2  = pk(KS, KS);
    const u64 NKS2 = pk(-KS, -KS);
    const u64 M2   = pk(-2.0f, -2.0f);

    const u64 s01 = pk(sc.x, sc.y), s23 = pk(sc.z, sc.w);
    const u64 na01 = mul2(NKS2, s01), na23 = mul2(NKS2, s23);  // -KS*sc
    const u64 pa01 = mul2(KS2,  s01), pa23 = mul2(KS2,  s23);  // +KS*sc
    const u64 yp01 = pk(yc.x, yc.y), yp23 = pk(yc.z, yc.w);
    const u64 m01 = mul2(M2, yp01), m23 = mul2(M2, yp23);      // -2*yp

    u64 acc01 = 0ull, acc23 = 0ull;

    // Unordered in-bounds pairs: positive offsets only, doubled at the end.
    // Branchless: OOB -> offset clamped to center, lw -> -1e30 => ex2 == 0.
    #pragma unroll
    for (int di = 0; di <= 3; ++di) {
        #pragma unroll
        for (int dj = -3; dj <= 3; ++dj) {
            if (di == 0 && dj <= 0) continue;
            const float lw = -(float)(di * di + dj * dj) * HALFL2E;
            const bool v = ((i + di) < H) & ((unsigned)(j + dj) < (unsigned)W);
            const int off = v ? (di * W + dj) * 16 : 0;
            const float lwv = v ? lw : NEGBIG;
            const u64 lw2 = pk(lwv, lwv);

            const float4 sq = s4[bs + off];
            const float4 yq = y4[by + off];
            const u64 sq01 = pk(sq.x, sq.y), sq23 = pk(sq.z, sq.w);
            const u64 yq01 = pk(yq.x, yq.y), yq23 = pk(yq.z, yq.w);

            const u64 t01  = fma2(KS2,  sq01, na01);   //  KS*(sq - sc)
            const u64 nt01 = fma2(NKS2, sq01, pa01);   // -KS*(sq - sc)
            const u64 w01  = fma2(t01, nt01, lw2);     // lw - t^2
            const u64 t23  = fma2(KS2,  sq23, na23);
            const u64 nt23 = fma2(NKS2, sq23, pa23);
            const u64 w23  = fma2(t23, nt23, lw2);

            float w0, w1, w2, w3;
            upk(w0, w1, w01); upk(w2, w3, w23);
            const u64 k01 = pk(ex2f(w0), ex2f(w1));
            const u64 k23 = pk(ex2f(w2), ex2f(w3));

            const u64 u01 = fma2(m01, yq01, add2(yp01, yq01));  // yp+yq-2*yp*yq
            const u64 u23 = fma2(m23, yq23, add2(yp23, yq23));

            acc01 = fma2(k01, u01, acc01);
            acc23 = fma2(k23, u23, acc23);
        }
    }

    float a0, a1, a2, a3;
    upk(a0, a1, acc01); upk(a2, a3, acc23);
    float acc = ((a0 + a1) + (a2 + a3)) * 2.0f;   // unordered -> directed

    // Out-of-bounds slots: neighbor features zero-padded ->
    // k_oob = exp(-0.5*(fr^2+fc^2+fs^2)), identical for every OOB slot of a pixel.
    {
        const int ir = min(i + 3, H - 1) - max(i - 3, 0) + 1;
        const int ic = min(j + 3, W - 1) - max(j - 3, 0) + 1;
        const float cnt = (float)(49 - ir * ic);
        if (cnt > 0.0f) {
            float na0, na1, na2, na3;
            upk(na0, na1, na01); upk(na2, na3, na23);
            const float cij = -(float)(i * i + j * j) * HALFL2E;
            float e = ex2f(fmaf(na0, -na0, cij))
                    + ex2f(fmaf(na1, -na1, cij))
                    + ex2f(fmaf(na2, -na2, cij))
                    + ex2f(fmaf(na3, -na3, cij));
            acc = fmaf(cnt, e, acc);
        }
    }

    // ---- Block tree reduction (deterministic) ----
    __shared__ float red[128];
    __shared__ bool is_last;
    const int tid = ty * 16 + d4;
    red[tid] = acc;
    __syncthreads();
    #pragma unroll
    for (int offr = 64; offr > 0; offr >>= 1) {
        if (tid < offr) red[tid] += red[tid + offr];
        __syncthreads();
    }

    // ---- Last-block-done global reduction (fixed order => deterministic) ----
    if (tid == 0) {
        g_partials[b] = red[0];
        __threadfence();
        unsigned int v = atomicAdd(&g_count, 1u);
        is_last = (v == (unsigned)(NBLK - 1));
    }
    __syncthreads();

    if (is_last) {
        __threadfence();
        __shared__ double dred[128];
        double sum = 0.0;
        #pragma unroll
        for (int k = 0; k < NBLK / 128; ++k)
            sum += (double)g_partials[tid + k * 128];
        dred[tid] = sum;
        __syncthreads();
        #pragma unroll
        for (int offr = 64; offr > 0; offr >>= 1) {
            if (tid < offr) dred[tid] += dred[tid + offr];
            __syncthreads();
        }
        if (tid == 0) {
            out[0] = (float)(dred[0] / (double)(NN * D * H * W));
            g_count = 0;   // reset for next graph replay
        }
    }
}

extern "C" void kernel_launch(void* const* d_in, const int* in_sizes, int n_in,
                              void* d_out, int out_size)
{
    const float* y = (const float*)d_in[0];   // (2,2,64,64,64) softmax
    const float* s = (const float*)d_in[1];   // (2,1,64,64,64) sample
    if (n_in >= 2 && in_sizes[0] == 2 * 1 * H * W * D) {
        const float* tmp = y; y = s; s = tmp;
    }

    dim3 blk(16, 8);
    crf_main<<<NBLK, blk>>>(y, s, (float*)d_out);
}